// round 1
// baseline (speedup 1.0000x reference)
#include <cuda_runtime.h>
#include <cuda_bf16.h>

// Problem constants
#define B_    8
#define H_    8
#define S_    4096
#define D_    64
#define DM_   768
#define SM2_  (S_ - 2)          // 4094
#define NROWS_ (B_ * SM2_)      // 32752
#define KTOT_ (H_ * D_)         // 512
#define EPS_        1e-8f
#define TRACE_LR_   0.1f
#define TRACE_DECAY_ 0.99f

// Scratch (allocation-free rule: __device__ globals). All fully rewritten each launch.
__device__ float g_GU[2][H_][D_][D_];   // [0]=G = Qhat^T Qhat, [1]=U = Qs^T Vs
__device__ float g_newT[H_][D_][D_];    // new_trace
__device__ float g_W2[DM_][KTOT_];      // W2[dm][h*64+p] = sum_q W_out[dm][h*64+q]*newT[h][p][q]

// ---------------------------------------------------------------------------
// K0: zero the G/U accumulators (graph replays reuse scratch -> must reset).
// 65536 floats = 16384 float4 = 64 blocks x 256 threads, one float4 each.
// ---------------------------------------------------------------------------
__global__ void k0_zero() {
    int idx = blockIdx.x * blockDim.x + threadIdx.x;
    ((float4*)g_GU)[idx] = make_float4(0.f, 0.f, 0.f, 0.f);
}

// ---------------------------------------------------------------------------
// K1: accumulate G[h] += qhat qhat^T and U[h] += q v^T over 32752 rows/head.
// grid (64 chunks, 8 heads), 256 threads. Batches of 8 rows staged in smem;
// each thread owns a 4x4 tile of the 64x64 outputs (16 G + 16 U accums).
// Block partials atomicAdd'ed to g_GU (64 partials per address -> cheap).
// ---------------------------------------------------------------------------
__global__ __launch_bounds__(256) void k1_acc(const float* __restrict__ Q,
                                              const float* __restrict__ V) {
    const int h = blockIdx.y;
    const int chunk = blockIdx.x;
    const int RPC = 512;
    const int r_begin = chunk * RPC;
    const int r_end = min(r_begin + RPC, NROWS_);

    __shared__ float sQ[8][64];
    __shared__ float sV[8][64];
    __shared__ float sInv[8];

    float gacc[16], uacc[16];
#pragma unroll
    for (int i = 0; i < 16; i++) { gacc[i] = 0.f; uacc[i] = 0.f; }

    const int tid = threadIdx.x;
    const int p0 = (tid >> 4) << 2;   // 0..60 step 4
    const int q0 = (tid & 15) << 2;   // 0..60 step 4

    for (int r0 = r_begin; r0 < r_end; r0 += 8) {
        const int nr = min(8, r_end - r0);
        // ---- stage 8 rows of Q and V (threads 0-127: Q, 128-255: V) ----
        {
            const int half = tid >> 7;
            const int t = tid & 127;
            const int rl = t >> 4;
            const int seg = t & 15;
            if (rl < nr) {
                const int r = r0 + rl;
                const int b = r / SM2_;
                const int i = r - b * SM2_;
                if (half == 0) {
                    float4 v = *(const float4*)(Q + ((b * H_ + h) * S_ + i) * D_ + seg * 4);
                    *(float4*)&sQ[rl][seg * 4] = v;
                } else {
                    float4 v = *(const float4*)(V + ((b * H_ + h) * S_ + (i + 2)) * D_ + seg * 4);
                    *(float4*)&sV[rl][seg * 4] = v;
                }
            }
        }
        __syncthreads();
        // ---- per-row inverse norms: warp w reduces row w ----
        {
            const int w = tid >> 5, lane = tid & 31;
            float x0 = sQ[w][lane], x1 = sQ[w][lane + 32];
            float ss = x0 * x0 + x1 * x1;
#pragma unroll
            for (int o = 16; o; o >>= 1) ss += __shfl_xor_sync(0xffffffffu, ss, o);
            if (lane == 0) sInv[w] = 1.0f / fmaxf(sqrtf(ss), EPS_);
        }
        __syncthreads();
        // ---- accumulate outer products ----
        for (int rl = 0; rl < nr; rl++) {
            const float inv = sInv[rl];
            const float4 qp = *(const float4*)&sQ[rl][p0];
            const float4 qq = *(const float4*)&sQ[rl][q0];
            const float4 vq = *(const float4*)&sV[rl][q0];
            float qph[4] = {qp.x * inv, qp.y * inv, qp.z * inv, qp.w * inv};
            float qqh[4] = {qq.x * inv, qq.y * inv, qq.z * inv, qq.w * inv};
            float qpa[4] = {qp.x, qp.y, qp.z, qp.w};
            float vqa[4] = {vq.x, vq.y, vq.z, vq.w};
#pragma unroll
            for (int a = 0; a < 4; a++)
#pragma unroll
                for (int c = 0; c < 4; c++) {
                    gacc[a * 4 + c] = fmaf(qph[a], qqh[c], gacc[a * 4 + c]);
                    uacc[a * 4 + c] = fmaf(qpa[a], vqa[c], uacc[a * 4 + c]);
                }
        }
        __syncthreads();
    }
#pragma unroll
    for (int a = 0; a < 4; a++)
#pragma unroll
        for (int c = 0; c < 4; c++) {
            atomicAdd(&g_GU[0][h][p0 + a][q0 + c], gacc[a * 4 + c]);
            atomicAdd(&g_GU[1][h][p0 + a][q0 + c], uacc[a * 4 + c]);
        }
}

// ---------------------------------------------------------------------------
// K2: new_trace = 0.99*(trace - G@trace/denom) + 0.1*U/denom. One block/head.
// ---------------------------------------------------------------------------
__global__ __launch_bounds__(256) void k2_newtrace(const float* __restrict__ trace) {
    const int h = blockIdx.x;
    __shared__ float sG[64][65];
    __shared__ float sT[64][65];
    const int tid = threadIdx.x;

    for (int j = 0; j < 16; j++) {
        int idx = tid + j * 256;          // 0..4095
        int p = idx >> 6, q = idx & 63;
        sG[p][q] = g_GU[0][h][p][q];
        sT[p][q] = trace[h * 4096 + idx];
    }
    __syncthreads();

    const float invden = 1.0f / (float)NROWS_;
    const int p = tid >> 2;
    const int qb = (tid & 3) * 16;
    float dot[16];
#pragma unroll
    for (int j = 0; j < 16; j++) dot[j] = 0.f;
    for (int k = 0; k < 64; k++) {
        const float gpk = sG[p][k];
#pragma unroll
        for (int j = 0; j < 16; j++) dot[j] = fmaf(gpk, sT[k][qb + j], dot[j]);
    }
#pragma unroll
    for (int j = 0; j < 16; j++) {
        const int q = qb + j;
        const float u = g_GU[1][h][p][q];
        g_newT[h][p][q] = TRACE_DECAY_ * (sT[p][q] - dot[j] * invden)
                        + TRACE_LR_ * u * invden;
    }
}

// ---------------------------------------------------------------------------
// K3: W2[dm][h*64+p] = sum_q W_out[dm][h*64+q] * newT[h][p][q].
// grid (8 heads, 12 dm-tiles of 64). 64x64x64 micro-GEMM per block from smem.
// ---------------------------------------------------------------------------
__global__ __launch_bounds__(256) void k3_w2(const float* __restrict__ W_out) {
    const int h = blockIdx.x;
    const int dm0 = blockIdx.y * 64;
    __shared__ float sW[64][64];    // W_out[dm0+i][h*64+q]
    __shared__ float sNT[64][65];   // newT[h][p][q], padded
    const int tid = threadIdx.x;

    for (int j = 0; j < 16; j++) {
        int idx = tid + j * 256;       // 0..4095
        int r = idx >> 6, q = idx & 63;
        sNT[r][q] = g_newT[h][r][q];
        sW[r][q] = W_out[(dm0 + r) * KTOT_ + h * 64 + q];
    }
    __syncthreads();

    for (int j = 0; j < 16; j++) {
        int o = tid + j * 256;         // 0..4095
        int dm_l = o >> 6, p = o & 63;
        float acc = 0.f;
#pragma unroll
        for (int q = 0; q < 64; q++) acc = fmaf(sW[dm_l][q], sNT[p][q], acc);
        g_W2[dm0 + dm_l][h * 64 + p] = acc;
    }
}

// ---------------------------------------------------------------------------
// K4: out[m, n] = sum_k A[m,k] * W2[n][k];  m=(b,s), k=h*64+p, n=dm.
// A[m,k] = (s>0) ? Q[b,h,s-1,p] : 0  (shift-by-1 addressed read, no copy).
// 128x128 block tile, BK=16, 8x8 register microtiles, 256 threads.
// M=32768, N=768, K=512 -> grid (6, 256), all dims exact.
// ---------------------------------------------------------------------------
__global__ __launch_bounds__(256, 2) void k4_gemm(const float* __restrict__ Q,
                                                  float* __restrict__ out) {
    __shared__ float As[16][128];
    __shared__ float Bs[16][128];

    const int tid = threadIdx.x;
    const int bn = blockIdx.x;        // 0..5
    const int bm = blockIdx.y;        // 0..255
    const int tx = tid & 15, ty = tid >> 4;
    const int m_base = bm * 128;
    const int n_base = bn * 128;

    float acc[8][8];
#pragma unroll
    for (int i = 0; i < 8; i++)
#pragma unroll
        for (int j = 0; j < 8; j++) acc[i][j] = 0.f;

    // A-load assignment: two rows per thread
    const int arow = tid >> 2;        // 0..63
    const int aseg = tid & 3;         // which float4 of the 16-wide k-slab
    const int m0 = m_base + arow;
    const int m1 = m_base + arow + 64;
    const int b0 = m0 >> 12, s0 = m0 & 4095;
    const int b1 = m1 >> 12, s1 = m1 & 4095;
    // B-load assignment: one n-row, two float4
    const int brow = tid >> 1;        // 0..127
    const int bsegb = (tid & 1) * 2;  // 0 or 2

    for (int k0 = 0; k0 < 512; k0 += 16) {
        const int h = k0 >> 6;
        const int pbase = (k0 & 63) + aseg * 4;

        float4 a0 = make_float4(0.f, 0.f, 0.f, 0.f);
        float4 a1 = a0;
        if (s0 > 0) a0 = *(const float4*)(Q + ((b0 * H_ + h) * S_ + (s0 - 1)) * D_ + pbase);
        if (s1 > 0) a1 = *(const float4*)(Q + ((b1 * H_ + h) * S_ + (s1 - 1)) * D_ + pbase);
        const float4 w0 = *(const float4*)&g_W2[n_base + brow][k0 + bsegb * 4];
        const float4 w1 = *(const float4*)&g_W2[n_base + brow][k0 + bsegb * 4 + 4];

        __syncthreads();   // previous tile's compute done before overwrite

        {
            const int ks = aseg * 4;
            As[ks + 0][arow] = a0.x; As[ks + 1][arow] = a0.y;
            As[ks + 2][arow] = a0.z; As[ks + 3][arow] = a0.w;
            As[ks + 0][arow + 64] = a1.x; As[ks + 1][arow + 64] = a1.y;
            As[ks + 2][arow + 64] = a1.z; As[ks + 3][arow + 64] = a1.w;
            const int kb = bsegb * 4;
            Bs[kb + 0][brow] = w0.x; Bs[kb + 1][brow] = w0.y;
            Bs[kb + 2][brow] = w0.z; Bs[kb + 3][brow] = w0.w;
            Bs[kb + 4][brow] = w1.x; Bs[kb + 5][brow] = w1.y;
            Bs[kb + 6][brow] = w1.z; Bs[kb + 7][brow] = w1.w;
        }
        __syncthreads();

#pragma unroll
        for (int kk = 0; kk < 16; kk++) {
            float a[8], bb[8];
            *(float4*)&a[0]  = *(const float4*)&As[kk][ty * 8];
            *(float4*)&a[4]  = *(const float4*)&As[kk][ty * 8 + 4];
            *(float4*)&bb[0] = *(const float4*)&Bs[kk][tx * 8];
            *(float4*)&bb[4] = *(const float4*)&Bs[kk][tx * 8 + 4];
#pragma unroll
            for (int i = 0; i < 8; i++)
#pragma unroll
                for (int j = 0; j < 8; j++)
                    acc[i][j] = fmaf(a[i], bb[j], acc[i][j]);
        }
    }

    // epilogue: coalesced float4 stores
#pragma unroll
    for (int i = 0; i < 8; i++) {
        const int m = m_base + ty * 8 + i;
        float* dst = out + (size_t)m * DM_ + n_base + tx * 8;
        float4 v0 = make_float4(acc[i][0], acc[i][1], acc[i][2], acc[i][3]);
        float4 v1 = make_float4(acc[i][4], acc[i][5], acc[i][6], acc[i][7]);
        *(float4*)dst = v0;
        *(float4*)(dst + 4) = v1;
    }
}

// ---------------------------------------------------------------------------
extern "C" void kernel_launch(void* const* d_in, const int* in_sizes, int n_in,
                              void* d_out, int out_size) {
    const float* Q     = (const float*)d_in[0];
    const float* V     = (const float*)d_in[1];
    const float* trace = (const float*)d_in[2];
    const float* W_out = (const float*)d_in[3];
    float* out = (float*)d_out;

    k0_zero<<<64, 256>>>();
    dim3 g1(64, H_);
    k1_acc<<<g1, 256>>>(Q, V);
    k2_newtrace<<<H_, 256>>>(trace);
    dim3 g3(H_, DM_ / 64);
    k3_w2<<<g3, 256>>>(W_out);
    dim3 g4(DM_ / 128, (B_ * S_) / 128);
    k4_gemm<<<g4, 256>>>(Q, out);
}

// round 3
// speedup vs baseline: 1.9619x; 1.9619x over previous
#include <cuda_runtime.h>
#include <cuda_bf16.h>
#include <cstdint>

// Problem constants
#define B_    8
#define H_    8
#define S_    4096
#define D_    64
#define DM_   768
#define SM2_  (S_ - 2)          // 4094
#define NROWS_ (B_ * SM2_)      // 32752
#define KTOT_ (H_ * D_)         // 512
#define EPS_        1e-8f
#define TRACE_LR_   0.1f
#define TRACE_DECAY_ 0.99f

// tcgen05 available only in the arch-accelerated compilation pass.
#if defined(__CUDA_ARCH_FEAT_SM103_ALL) || defined(__CUDA_ARCH_FEAT_SM100_ALL) || defined(__CUDA_ARCH_FEAT_SM101_ALL)
#define TC_OK 1
#else
#define TC_OK 0
#endif

// Scratch (allocation-free rule: __device__ globals). All fully rewritten each launch.
__device__ float g_GU[2][H_][D_][D_];            // [0]=G = Qhat^T Qhat, [1]=U = Qs^T Vs
__device__ float g_newT[H_][D_][D_];             // new_trace
__device__ __nv_bfloat16 g_W2h[DM_][KTOT_];      // hi part of W2
__device__ __nv_bfloat16 g_W2l[DM_][KTOT_];      // lo part of W2

// ---------------------------------------------------------------------------
// small helpers
// ---------------------------------------------------------------------------
__device__ __forceinline__ uint32_t smem_u32(const void* p) {
    uint32_t a;
    asm("{ .reg .u64 t; cvta.to.shared.u64 t, %1; cvt.u32.u64 %0, t; }" : "=r"(a) : "l"(p));
    return a;
}
__device__ __forceinline__ unsigned long long pack2(float lo, float hi) {
    unsigned long long r;
    asm("mov.b64 %0, {%1, %2};" : "=l"(r) : "f"(lo), "f"(hi));
    return r;
}
__device__ __forceinline__ void unpack2(unsigned long long v, float& lo, float& hi) {
    asm("mov.b64 {%0, %1}, %2;" : "=f"(lo), "=f"(hi) : "l"(v));
}
__device__ __forceinline__ void fma2(unsigned long long& d, unsigned long long a, unsigned long long b) {
    asm("fma.rn.f32x2 %0, %1, %2, %3;" : "=l"(d) : "l"(a), "l"(b), "l"(d));
}
__device__ __forceinline__ void mul2(unsigned long long& d, unsigned long long a, unsigned long long b) {
    asm("mul.rn.f32x2 %0, %1, %2;" : "=l"(d) : "l"(a), "l"(b));
}
__device__ __forceinline__ float bf16lo(uint32_t u) {
    return __bfloat162float(__ushort_as_bfloat16((unsigned short)(u & 0xffffu)));
}
__device__ __forceinline__ float bf16hi(uint32_t u) {
    return __bfloat162float(__ushort_as_bfloat16((unsigned short)(u >> 16)));
}

#define MBAR_INIT(a, n) asm volatile("mbarrier.init.shared.b64 [%0], %1;" :: "r"(a), "r"(n) : "memory")
#define MBAR_INVAL(a)   asm volatile("mbarrier.inval.shared.b64 [%0];" :: "r"(a) : "memory")
#define MBAR_WAIT(a, ph) do {                                                         \
    uint32_t _m = (a); uint32_t _p = (ph); uint32_t _d;                               \
    asm volatile("{\n\t.reg .pred p;\n\t"                                             \
        "mbarrier.try_wait.parity.acquire.cta.shared::cta.b64 p, [%1], %2;\n\t"       \
        "selp.b32 %0, 1, 0, p;\n\t}" : "=r"(_d) : "r"(_m), "r"(_p) : "memory");       \
    if (!_d) {                                                                        \
        asm volatile("{\n\t.reg .pred P1;\n\t"                                        \
            "WL_%=:\n\t"                                                              \
            "mbarrier.try_wait.parity.acquire.cta.shared::cta.b64 P1, [%0], %1, 0x989680;\n\t" \
            "@P1 bra.uni WD_%=;\n\t"                                                  \
            "bra.uni WL_%=;\n\t"                                                      \
            "WD_%=:\n\t}" :: "r"(_m), "r"(_p) : "memory");                            \
    }                                                                                 \
} while (0)

#if TC_OK
// SW128 smem descriptor (layout=2, version=1, SBO=64, LBO=1)
__device__ __forceinline__ uint64_t mkdesc(uint32_t addr) {
    return ((uint64_t)2 << 61) | ((uint64_t)1 << 46) | ((uint64_t)64 << 32) |
           ((uint64_t)1 << 16) | (uint64_t)((addr >> 4) & 0x3FFF);
}
__device__ __forceinline__ void tc_alloc(uint32_t smem_dst, uint32_t ncols) {
    asm volatile("tcgen05.alloc.cta_group::1.sync.aligned.shared::cta.b32 [%0], %1;"
                 :: "r"(smem_dst), "r"(ncols) : "memory");
}
__device__ __forceinline__ void tc_dealloc(uint32_t tmem, uint32_t ncols) {
    asm volatile("tcgen05.dealloc.cta_group::1.sync.aligned.b32 %0, %1;" :: "r"(tmem), "r"(ncols));
}
__device__ __forceinline__ void tc_commit(uint32_t mbar) {
    asm volatile("tcgen05.commit.cta_group::1.mbarrier::arrive::one.shared::cluster.b64 [%0];"
                 :: "r"(mbar) : "memory");
}
// SS-mode cg1 kind::f16 (bf16 in, fp32 acc). idesc: F32|BF16|BF16|N=128|M=128.
__device__ __forceinline__ void tc_mma_ss(uint32_t d, uint64_t ad, uint64_t bd,
                                          uint32_t idesc, uint32_t en) {
    asm volatile("{\n\t.reg .pred p;\n\tsetp.ne.u32 p, %5, 0;\n\t"
                 "tcgen05.mma.cta_group::1.kind::f16 [%0], %1, %2, %3, {%4, %4, %4, %4}, p;\n\t}"
                 :: "r"(d), "l"(ad), "l"(bd), "r"(idesc), "r"(0u), "r"(en) : "memory");
}
#define K4_IDESC 0x8200490u
#endif // TC_OK

// ---------------------------------------------------------------------------
// K0: zero G/U accumulators (graph replays reuse scratch -> must reset).
// ---------------------------------------------------------------------------
__global__ void k0_zero() {
    int idx = blockIdx.x * blockDim.x + threadIdx.x;
    ((float4*)g_GU)[idx] = make_float4(0.f, 0.f, 0.f, 0.f);
}

// ---------------------------------------------------------------------------
// K1: accumulate G[h] += qhat qhat^T, U[h] += q v^T (packed f32x2 FMA).
// ---------------------------------------------------------------------------
__global__ __launch_bounds__(256) void k1_acc(const float* __restrict__ Q,
                                              const float* __restrict__ V) {
    const int h = blockIdx.y;
    const int chunk = blockIdx.x;
    const int RPC = 512;
    const int r_begin = chunk * RPC;
    const int r_end = min(r_begin + RPC, NROWS_);

    __shared__ float sQ[8][64];
    __shared__ float sV[8][64];
    __shared__ float sInv[8];

    unsigned long long g2[8], u2[8];
    const unsigned long long zz = pack2(0.f, 0.f);
#pragma unroll
    for (int i = 0; i < 8; i++) { g2[i] = zz; u2[i] = zz; }

    const int tid = threadIdx.x;
    const int p0 = (tid >> 4) << 2;
    const int q0 = (tid & 15) << 2;

    for (int r0 = r_begin; r0 < r_end; r0 += 8) {
        const int nr = min(8, r_end - r0);
        {
            const int half = tid >> 7;
            const int t = tid & 127;
            const int rl = t >> 4;
            const int seg = t & 15;
            if (rl < nr) {
                const int r = r0 + rl;
                const int b = r / SM2_;
                const int i = r - b * SM2_;
                if (half == 0) {
                    float4 v = *(const float4*)(Q + ((b * H_ + h) * S_ + i) * D_ + seg * 4);
                    *(float4*)&sQ[rl][seg * 4] = v;
                } else {
                    float4 v = *(const float4*)(V + ((b * H_ + h) * S_ + (i + 2)) * D_ + seg * 4);
                    *(float4*)&sV[rl][seg * 4] = v;
                }
            }
        }
        __syncthreads();
        {
            const int w = tid >> 5, lane = tid & 31;
            float x0 = sQ[w][lane], x1 = sQ[w][lane + 32];
            float ss = x0 * x0 + x1 * x1;
#pragma unroll
            for (int o = 16; o; o >>= 1) ss += __shfl_xor_sync(0xffffffffu, ss, o);
            if (lane == 0) sInv[w] = 1.0f / fmaxf(sqrtf(ss), EPS_);
        }
        __syncthreads();
        for (int rl = 0; rl < nr; rl++) {
            const float inv = sInv[rl];
            const float4 qp = *(const float4*)&sQ[rl][p0];
            const float4 qq = *(const float4*)&sQ[rl][q0];
            const float4 vq = *(const float4*)&sV[rl][q0];
            const unsigned long long inv2 = pack2(inv, inv);
            unsigned long long bqh01, bqh23;
            mul2(bqh01, pack2(qq.x, qq.y), inv2);
            mul2(bqh23, pack2(qq.z, qq.w), inv2);
            const unsigned long long bv01 = pack2(vq.x, vq.y);
            const unsigned long long bv23 = pack2(vq.z, vq.w);
            const float qpa[4] = {qp.x, qp.y, qp.z, qp.w};
#pragma unroll
            for (int a = 0; a < 4; a++) {
                const float qh = qpa[a] * inv;
                const unsigned long long a2h = pack2(qh, qh);
                const unsigned long long a2 = pack2(qpa[a], qpa[a]);
                fma2(g2[a * 2 + 0], a2h, bqh01);
                fma2(g2[a * 2 + 1], a2h, bqh23);
                fma2(u2[a * 2 + 0], a2, bv01);
                fma2(u2[a * 2 + 1], a2, bv23);
            }
        }
        __syncthreads();
    }
#pragma unroll
    for (int a = 0; a < 4; a++)
#pragma unroll
        for (int j = 0; j < 2; j++) {
            float lo, hi;
            unpack2(g2[a * 2 + j], lo, hi);
            atomicAdd(&g_GU[0][h][p0 + a][q0 + 2 * j + 0], lo);
            atomicAdd(&g_GU[0][h][p0 + a][q0 + 2 * j + 1], hi);
            unpack2(u2[a * 2 + j], lo, hi);
            atomicAdd(&g_GU[1][h][p0 + a][q0 + 2 * j + 0], lo);
            atomicAdd(&g_GU[1][h][p0 + a][q0 + 2 * j + 1], hi);
        }
}

// ---------------------------------------------------------------------------
// K2: new_trace = 0.99*(trace - G@trace/denom) + 0.1*U/denom. One block/head.
// ---------------------------------------------------------------------------
__global__ __launch_bounds__(256) void k2_newtrace(const float* __restrict__ trace) {
    const int h = blockIdx.x;
    __shared__ float sG[64][65];
    __shared__ float sT[64][65];
    const int tid = threadIdx.x;

    for (int j = 0; j < 16; j++) {
        int idx = tid + j * 256;
        int p = idx >> 6, q = idx & 63;
        sG[p][q] = g_GU[0][h][p][q];
        sT[p][q] = trace[h * 4096 + idx];
    }
    __syncthreads();

    const float invden = 1.0f / (float)NROWS_;
    const int p = tid >> 2;
    const int qb = (tid & 3) * 16;
    float dot[16];
#pragma unroll
    for (int j = 0; j < 16; j++) dot[j] = 0.f;
    for (int k = 0; k < 64; k++) {
        const float gpk = sG[p][k];
#pragma unroll
        for (int j = 0; j < 16; j++) dot[j] = fmaf(gpk, sT[k][qb + j], dot[j]);
    }
#pragma unroll
    for (int j = 0; j < 16; j++) {
        const int q = qb + j;
        const float u = g_GU[1][h][p][q];
        g_newT[h][p][q] = TRACE_DECAY_ * (sT[p][q] - dot[j] * invden)
                        + TRACE_LR_ * u * invden;
    }
}

// ---------------------------------------------------------------------------
// K3: W2[dm][h*64+p] = sum_q W_out[dm][h*64+q]*newT[h][p][q], bf16 hi/lo split.
// ---------------------------------------------------------------------------
__global__ __launch_bounds__(256) void k3_w2(const float* __restrict__ W_out) {
    const int h = blockIdx.x;
    const int dm0 = blockIdx.y * 64;
    __shared__ float sW[64][64];
    __shared__ float sNT[64][65];
    const int tid = threadIdx.x;

    for (int j = 0; j < 16; j++) {
        int idx = tid + j * 256;
        int r = idx >> 6, q = idx & 63;
        sNT[r][q] = g_newT[h][r][q];
        sW[r][q] = W_out[(dm0 + r) * KTOT_ + h * 64 + q];
    }
    __syncthreads();

    for (int j = 0; j < 16; j++) {
        int o = tid + j * 256;
        int dm_l = o >> 6, p = o & 63;
        float acc = 0.f;
#pragma unroll
        for (int q = 0; q < 64; q++) acc = fmaf(sW[dm_l][q], sNT[p][q], acc);
        __nv_bfloat16 hbits = __float2bfloat16(acc);
        float hf = __bfloat162float(hbits);
        g_W2h[dm0 + dm_l][h * 64 + p] = hbits;
        g_W2l[dm0 + dm_l][h * 64 + p] = __float2bfloat16(acc - hf);
    }
}

// ---------------------------------------------------------------------------
// K4: out[m,n] = sum_k A[m,k]*W2[n,k];  A[m, h*64+p] = (s>0) ? Q[b,h,s-1,p] : 0.
// Accelerated body: tcgen05 bf16-split (Ah*Bh + Ah*Bl + Al*Bh), M=256 tile
//   (two cg1 M=128 MMAs), N=128, K-chunk=64, double-buffered SW128 smem.
// Plain-target fallback body: SIMT 8x8-microtile GEMM (two 128-row halves).
// Launch config identical for both: grid (6, 128), 256 threads, 197632B dyn smem.
// ---------------------------------------------------------------------------
#define K4_BUFBYTES 98304
#define K4_SMEM (2 * K4_BUFBYTES + 1024)

#if TC_OK
__device__ __forceinline__ void k4_load_chunk(const float* __restrict__ Q, char* sm,
                                              int bufoff, int ch, int m_base, int n_base,
                                              int tid) {
    char* Ah = sm + bufoff;
    char* Al = sm + bufoff + 32768;
#pragma unroll
    for (int j = 0; j < 16; j++) {
        int idx = j * 256 + tid;
        int r = idx >> 4, seg = idx & 15;
        int m = m_base + r, b = m >> 12, s = m & 4095;
        float4 v = make_float4(0.f, 0.f, 0.f, 0.f);
        if (s > 0) v = *(const float4*)(Q + ((size_t)((b * H_ + ch) * S_ + (s - 1))) * D_ + seg * 4);
        __nv_bfloat16 h0 = __float2bfloat16(v.x), h1 = __float2bfloat16(v.y);
        __nv_bfloat16 h2 = __float2bfloat16(v.z), h3 = __float2bfloat16(v.w);
        uint32_t hp0 = (uint32_t)__bfloat16_as_ushort(h0) | ((uint32_t)__bfloat16_as_ushort(h1) << 16);
        uint32_t hp1 = (uint32_t)__bfloat16_as_ushort(h2) | ((uint32_t)__bfloat16_as_ushort(h3) << 16);
        __nv_bfloat16 l0 = __float2bfloat16(v.x - __bfloat162float(h0));
        __nv_bfloat16 l1 = __float2bfloat16(v.y - __bfloat162float(h1));
        __nv_bfloat16 l2 = __float2bfloat16(v.z - __bfloat162float(h2));
        __nv_bfloat16 l3 = __float2bfloat16(v.w - __bfloat162float(h3));
        uint32_t lp0 = (uint32_t)__bfloat16_as_ushort(l0) | ((uint32_t)__bfloat16_as_ushort(l1) << 16);
        uint32_t lp1 = (uint32_t)__bfloat16_as_ushort(l2) | ((uint32_t)__bfloat16_as_ushort(l3) << 16);
        uint32_t off = r * 128 + seg * 8;
        uint32_t sw = off ^ ((off >> 3) & 0x70);
        *(uint2*)(Ah + sw) = make_uint2(hp0, hp1);
        *(uint2*)(Al + sw) = make_uint2(lp0, lp1);
    }
    char* Bh = sm + bufoff + 65536;
    char* Bl = sm + bufoff + 81920;
#pragma unroll
    for (int j = 0; j < 8; j++) {
        int idx = j * 256 + tid;
        int arr = idx >> 10, rem = idx & 1023;
        int r = rem >> 3, seg = rem & 7;
        const __nv_bfloat16* srcrow =
            arr ? &g_W2l[n_base + r][ch * 64] : &g_W2h[n_base + r][ch * 64];
        uint4 v = ((const uint4*)srcrow)[seg];
        uint32_t off = r * 128 + seg * 16;
        uint32_t sw = off ^ ((off >> 3) & 0x70);
        *(uint4*)((arr ? Bl : Bh) + sw) = v;
    }
    asm volatile("fence.proxy.async.shared::cta;" ::: "memory");
}
#endif // TC_OK

__global__ __launch_bounds__(256, 1) void k4_tc(const float* __restrict__ Q,
                                                float* __restrict__ out) {
    extern __shared__ char dyn[];
    const int tid = threadIdx.x;
#if TC_OK
    char* sm = (char*)(((uintptr_t)dyn + 1023) & ~(uintptr_t)1023);
    const uint32_t smb = smem_u32(sm);
    __shared__ uint32_t s_tmem;
    __shared__ uint64_t s_mbar[2];

    const int wid = tid >> 5, lane = tid & 31;
    const int n_base = blockIdx.x * 128;
    const int m_base = blockIdx.y * 256;

    if (wid == 0) tc_alloc(smem_u32(&s_tmem), 256);
    if (tid == 0) { MBAR_INIT(smem_u32(&s_mbar[0]), 1); MBAR_INIT(smem_u32(&s_mbar[1]), 1); }
    __syncthreads();
    const uint32_t tb = s_tmem;
    const uint32_t mb[2] = {smem_u32(&s_mbar[0]), smem_u32(&s_mbar[1])};

    k4_load_chunk(Q, sm, 0, 0, m_base, n_base, tid);
    __syncthreads();

    for (int c = 0; c < 8; c++) {
        const int buf = c & 1;
        if (tid == 0) {
            const uint32_t bo = smb + buf * K4_BUFBYTES;
#pragma unroll
            for (int mh = 0; mh < 2; mh++) {
                const uint32_t dD = tb + mh * 128;
#pragma unroll
                for (int pr = 0; pr < 3; pr++) {
                    // pairs: (Ah,Bh), (Ah,Bl), (Al,Bh)
                    const uint32_t aoff = (pr == 2 ? 32768u : 0u) + (uint32_t)mh * 16384u;
                    const uint32_t boff = (pr == 1 ? 81920u : 65536u);
                    const uint64_t ad = mkdesc(bo + aoff);
                    const uint64_t bd = mkdesc(bo + boff);
#pragma unroll
                    for (int ks = 0; ks < 4; ks++) {
                        const uint32_t en = (c == 0 && pr == 0 && ks == 0) ? 0u : 1u;
                        tc_mma_ss(dD, ad + ks * 2, bd + ks * 2, K4_IDESC, en);
                    }
                }
            }
            tc_commit(mb[buf]);
        }
        if (c < 7) {
            if (c >= 1) MBAR_WAIT(mb[1 - buf], ((c - 1) >> 1) & 1);
            k4_load_chunk(Q, sm, (1 - buf) * K4_BUFBYTES, c + 1, m_base, n_base, tid);
        }
        __syncthreads();
    }

    // chunk 7 = 4th commit on mb[1] -> completes phase 3 -> wait parity 1
    MBAR_WAIT(mb[1], 1);
    asm volatile("tcgen05.fence::after_thread_sync;" ::: "memory");

    {
        const int mh = wid >> 2;
        const int m = m_base + mh * 128 + (wid & 3) * 32 + lane;
        const uint32_t dbase = tb + mh * 128;
#pragma unroll
        for (int nb = 0; nb < 128; nb += 32) {
            uint32_t dr[32];
            asm volatile(
                "tcgen05.ld.sync.aligned.32x32b.x32.b32 "
                "{%0,%1,%2,%3,%4,%5,%6,%7,%8,%9,%10,%11,%12,%13,%14,%15,"
                "%16,%17,%18,%19,%20,%21,%22,%23,%24,%25,%26,%27,%28,%29,%30,%31}, [%32];"
                : "=r"(dr[0]), "=r"(dr[1]), "=r"(dr[2]), "=r"(dr[3]),
                  "=r"(dr[4]), "=r"(dr[5]), "=r"(dr[6]), "=r"(dr[7]),
                  "=r"(dr[8]), "=r"(dr[9]), "=r"(dr[10]), "=r"(dr[11]),
                  "=r"(dr[12]), "=r"(dr[13]), "=r"(dr[14]), "=r"(dr[15]),
                  "=r"(dr[16]), "=r"(dr[17]), "=r"(dr[18]), "=r"(dr[19]),
                  "=r"(dr[20]), "=r"(dr[21]), "=r"(dr[22]), "=r"(dr[23]),
                  "=r"(dr[24]), "=r"(dr[25]), "=r"(dr[26]), "=r"(dr[27]),
                  "=r"(dr[28]), "=r"(dr[29]), "=r"(dr[30]), "=r"(dr[31])
                : "r"(dbase + nb));
            asm volatile("tcgen05.wait::ld.sync.aligned;" ::: "memory");
            float* dst = out + (size_t)m * DM_ + n_base + nb;
#pragma unroll
            for (int k = 0; k < 8; k++) {
                ((float4*)dst)[k] = make_float4(
                    __uint_as_float(dr[k * 4 + 0]), __uint_as_float(dr[k * 4 + 1]),
                    __uint_as_float(dr[k * 4 + 2]), __uint_as_float(dr[k * 4 + 3]));
            }
        }
    }
    asm volatile("tcgen05.fence::before_thread_sync;" ::: "memory");
    __syncthreads();
    if (tid == 0) { MBAR_INVAL(mb[0]); MBAR_INVAL(mb[1]); }
    __syncthreads();
    if (wid == 0) tc_dealloc(tb, 256);
#else
    // ---------------- SIMT fallback (plain compute_103 pass) ----------------
    float (*As)[128] = (float(*)[128])dyn;           // [16][128]
    float (*Bs)[128] = (float(*)[128])(dyn + 8192);  // [16][128]
    const int tx = tid & 15, ty = tid >> 4;
    const int n_base = blockIdx.x * 128;
    const int arow = tid >> 2, aseg = tid & 3;
    const int brow = tid >> 1, bsegb = (tid & 1) * 2;

    for (int half = 0; half < 2; half++) {
        const int m_base = blockIdx.y * 256 + half * 128;
        float acc[8][8];
#pragma unroll
        for (int i = 0; i < 8; i++)
#pragma unroll
            for (int j = 0; j < 8; j++) acc[i][j] = 0.f;

        const int m0 = m_base + arow;
        const int m1 = m_base + arow + 64;
        const int b0 = m0 >> 12, s0 = m0 & 4095;
        const int b1 = m1 >> 12, s1 = m1 & 4095;

        for (int k0 = 0; k0 < 512; k0 += 16) {
            const int h = k0 >> 6;
            const int pbase = (k0 & 63) + aseg * 4;
            float4 a0 = make_float4(0.f, 0.f, 0.f, 0.f);
            float4 a1 = a0;
            if (s0 > 0) a0 = *(const float4*)(Q + ((b0 * H_ + h) * S_ + (s0 - 1)) * D_ + pbase);
            if (s1 > 0) a1 = *(const float4*)(Q + ((b1 * H_ + h) * S_ + (s1 - 1)) * D_ + pbase);
            const uint4 wh = *(const uint4*)&g_W2h[n_base + brow][k0 + bsegb * 4];
            const uint4 wl = *(const uint4*)&g_W2l[n_base + brow][k0 + bsegb * 4];
            float wv[8];
            const uint32_t* whp = (const uint32_t*)&wh;
            const uint32_t* wlp = (const uint32_t*)&wl;
#pragma unroll
            for (int j = 0; j < 4; j++) {
                wv[j * 2 + 0] = bf16lo(whp[j]) + bf16lo(wlp[j]);
                wv[j * 2 + 1] = bf16hi(whp[j]) + bf16hi(wlp[j]);
            }
            __syncthreads();
            {
                const int ks = aseg * 4;
                As[ks + 0][arow] = a0.x; As[ks + 1][arow] = a0.y;
                As[ks + 2][arow] = a0.z; As[ks + 3][arow] = a0.w;
                As[ks + 0][arow + 64] = a1.x; As[ks + 1][arow + 64] = a1.y;
                As[ks + 2][arow + 64] = a1.z; As[ks + 3][arow + 64] = a1.w;
                const int kb = bsegb * 4;
#pragma unroll
                for (int j = 0; j < 8; j++) Bs[kb + j][brow] = wv[j];
            }
            __syncthreads();
#pragma unroll
            for (int kk = 0; kk < 16; kk++) {
                float a[8], bb[8];
                *(float4*)&a[0]  = *(const float4*)&As[kk][ty * 8];
                *(float4*)&a[4]  = *(const float4*)&As[kk][ty * 8 + 4];
                *(float4*)&bb[0] = *(const float4*)&Bs[kk][tx * 8];
                *(float4*)&bb[4] = *(const float4*)&Bs[kk][tx * 8 + 4];
#pragma unroll
                for (int i = 0; i < 8; i++)
#pragma unroll
                    for (int j = 0; j < 8; j++)
                        acc[i][j] = fmaf(a[i], bb[j], acc[i][j]);
            }
        }
#pragma unroll
        for (int i = 0; i < 8; i++) {
            const int m = m_base + ty * 8 + i;
            float* dst = out + (size_t)m * DM_ + n_base + tx * 8;
            *(float4*)dst = make_float4(acc[i][0], acc[i][1], acc[i][2], acc[i][3]);
            *(float4*)(dst + 4) = make_float4(acc[i][4], acc[i][5], acc[i][6], acc[i][7]);
        }
        __syncthreads();
    }
#endif
}

// ---------------------------------------------------------------------------
extern "C" void kernel_launch(void* const* d_in, const int* in_sizes, int n_in,
                              void* d_out, int out_size) {
    const float* Q     = (const float*)d_in[0];
    const float* V     = (const float*)d_in[1];
    const float* trace = (const float*)d_in[2];
    const float* W_out = (const float*)d_in[3];
    float* out = (float*)d_out;

    cudaFuncSetAttribute(k4_tc, cudaFuncAttributeMaxDynamicSharedMemorySize, K4_SMEM);

    k0_zero<<<64, 256>>>();
    dim3 g1(64, H_);
    k1_acc<<<g1, 256>>>(Q, V);
    k2_newtrace<<<H_, 256>>>(trace);
    dim3 g3(H_, DM_ / 64);
    k3_w2<<<g3, 256>>>(W_out);
    dim3 g4(DM_ / 128, (B_ * S_) / 256);
    k4_tc<<<g4, 256, K4_SMEM>>>(Q, out);
}